// round 6
// baseline (speedup 1.0000x reference)
#include <cuda_runtime.h>

#define T_SEQ   2048
#define BATCH   64
#define INP     16
#define HEADS   8
#define HID     64
#define GATES   256
#define BC      4
#define NTHREADS 512
#define OUT_ELEMS  (T_SEQ * BATCH * HEADS)
#define LOUT_ELEMS (T_SEQ * BATCH * HID)

// Packed fp32x2 FMA (sm_100+): 2 MACs/instr, 2x FFMA throughput.
__device__ __forceinline__ float2 ffma2(float2 a, float2 b, float2 c) {
    float2 d;
    asm("fma.rn.f32x2 %0, %1, %2, %3;"
        : "=l"(reinterpret_cast<unsigned long long&>(d))
        : "l"(reinterpret_cast<const unsigned long long&>(a)),
          "l"(reinterpret_cast<const unsigned long long&>(b)),
          "l"(reinterpret_cast<const unsigned long long&>(c)));
    return d;
}

__device__ __forceinline__ float fsig(float x) {
    return __fdividef(1.0f, 1.0f + __expf(-x));
}
__device__ __forceinline__ float ftanh_(float x) {
    return fmaf(2.0f, fsig(2.0f * x), -1.0f);
}

// Thread layout (512 threads, 16 warps):
//   lane bits: [0:2)=dlow, [2:4)=g (gate), [4]=kh (k-half)
//   warp w in [0,16): d = w*4 + dlow, gate row = g*64 + d
// Each thread: one gate row, one k-half (32 of 64 hh-k, 8 of 16 ih-k),
// all 4 batches. z combined across kh by shfl_xor(16), then 4x4
// gate-batch transpose over lane bits 2-3 -> thread owns batch bb=g.
// One __syncthreads per step (hs/red double-buffered).
__global__ void __launch_bounds__(NTHREADS)
lstm_kernel(const float* __restrict__ x,    const float* __restrict__ Wih,
            const float* __restrict__ Whh,  const float* __restrict__ bih,
            const float* __restrict__ bhh,  const float* __restrict__ Wlin,
            const float* __restrict__ blin, float* __restrict__ out,
            float* __restrict__ lout)
{
    const int h    = blockIdx.x >> 4;
    const int b0   = (blockIdx.x & 15) * BC;
    const int tid  = threadIdx.x;
    const int l    = tid & 31;
    const int w    = tid >> 5;
    const int dlow = l & 3;
    const int g    = (l >> 2) & 3;
    const int kh   = l >> 4;
    const int d    = w * 4 + dlow;
    const int row  = g * HID + d;

    __shared__ __align__(16) float hs[2][BC * HID];   // [buf][bb*64+d]
    __shared__ __align__(16) float xs[2][BC * INP];   // x double buffer
    __shared__ float red[2][64];                      // [buf][g*16+w]

    // ---- weights -> registers (row, k-half) ----
    float2 w2[16];
    {
        const float4* wr = reinterpret_cast<const float4*>(
            Whh + ((size_t)(h * GATES + row)) * HID + kh * 32);
#pragma unroll
        for (int q = 0; q < 8; ++q) {
            float4 v = wr[q];
            w2[2 * q]     = make_float2(v.x, v.y);
            w2[2 * q + 1] = make_float2(v.z, v.w);
        }
    }
    float2 wi2[4];
    {
        const float4* wr = reinterpret_cast<const float4*>(
            Wih + ((size_t)(h * GATES + row)) * INP + kh * 8);
#pragma unroll
        for (int q = 0; q < 2; ++q) {
            float4 v = wr[q];
            wi2[2 * q]     = make_float2(v.x, v.y);
            wi2[2 * q + 1] = make_float2(v.z, v.w);
        }
    }
    const float bias   = (kh == 0) ? (bih[h * GATES + row] + bhh[h * GATES + row]) : 0.0f;
    const float wlin_d = Wlin[h * HID + d];
    const float blin_v = blin[h];

    // ---- init ----
    if (tid < BC * HID) { hs[0][tid] = 0.0f; hs[1][tid] = 0.0f; }
    float c = 0.0f;
    float xreg = 0.0f;
    if (tid < BC * INP) {
        xs[0][tid] = x[(size_t)0 * BATCH * INP + b0 * INP + tid];
        xreg       = x[(size_t)1 * BATCH * INP + b0 * INP + tid];
    }
    __syncthreads();

    for (int t = 0; t < T_SEQ; ++t) {
        // deferred out[t-1]: red[(t-1)&1] finalized last step, stable now
        if (t > 0 && tid < 64) {
            float p = red[(t - 1) & 1][tid];   // tid = g*16 + w, bits 0-3 = w
#pragma unroll
            for (int s = 8; s; s >>= 1) p += __shfl_xor_sync(0xffffffffu, p, s);
            if ((tid & 15) == 0)
                out[(size_t)((t - 1) * BATCH + b0 + (tid >> 4)) * HEADS + h] = p + blin_v;
        }

        // ---- phase 1: partial z for 4 batches (this thread's k-half) ----
        const float* hb = hs[t & 1];
        const float* xb = xs[t & 1];
        float z[4];
#pragma unroll
        for (int b = 0; b < BC; ++b) {
            float2 a0 = make_float2(bias, 0.0f);
            float2 a1 = make_float2(0.0f, 0.0f);
            const float4* hv = reinterpret_cast<const float4*>(hb + b * HID + kh * 32);
#pragma unroll
            for (int q = 0; q < 8; ++q) {
                float4 v = hv[q];
                a0 = ffma2(w2[2 * q],     make_float2(v.x, v.y), a0);
                a1 = ffma2(w2[2 * q + 1], make_float2(v.z, v.w), a1);
            }
            const float4* xv = reinterpret_cast<const float4*>(xb + b * INP + kh * 8);
#pragma unroll
            for (int q = 0; q < 2; ++q) {
                float4 v = xv[q];
                a0 = ffma2(wi2[2 * q],     make_float2(v.x, v.y), a0);
                a1 = ffma2(wi2[2 * q + 1], make_float2(v.z, v.w), a1);
            }
            z[b] = (a0.x + a0.y) + (a1.x + a1.y);
        }

        // ---- combine k-halves (both copies get full sum; bias counted once) ----
#pragma unroll
        for (int b = 0; b < BC; ++b)
            z[b] += __shfl_xor_sync(0xffffffffu, z[b], 16);

        // ---- 4x4 gate-batch butterfly transpose over lane bits 2-3 ----
        {
            float s0, s1, r0, r1;
            s0 = (g & 1) ? z[0] : z[1];
            s1 = (g & 1) ? z[2] : z[3];
            r0 = __shfl_xor_sync(0xffffffffu, s0, 4);
            r1 = __shfl_xor_sync(0xffffffffu, s1, 4);
            if (g & 1) { z[0] = r0; z[2] = r1; } else { z[1] = r0; z[3] = r1; }
            s0 = (g & 2) ? z[0] : z[2];
            s1 = (g & 2) ? z[1] : z[3];
            r0 = __shfl_xor_sync(0xffffffffu, s0, 8);
            r1 = __shfl_xor_sync(0xffffffffu, s1, 8);
            if (g & 2) { z[0] = r0; z[1] = r1; } else { z[2] = r0; z[3] = r1; }
        }
        // now z = {zi, zf, zg, zo} for batch bb = g, hidden d

        // ---- phase 2: gates + state (both kh copies compute identically) ----
        float ig = fsig(z[0]) * ftanh_(z[2]);
        c = fmaf(fsig(z[1]), c, ig);
        float hval = fsig(z[3]) * ftanh_(c);

        if (kh == 0) {
            hs[(t + 1) & 1][g * HID + d] = hval;
            atomicAdd(lout + (size_t)(t * BATCH + b0 + g) * HID + d, hval);
        }

        // per-head linear partial: sum over dlow (lane bits 0-1)
        float p = hval * wlin_d;
        p += __shfl_xor_sync(0xffffffffu, p, 1);
        p += __shfl_xor_sync(0xffffffffu, p, 2);
        if (kh == 0 && dlow == 0) red[t & 1][g * 16 + w] = p;

        // x pipeline
        if (tid < BC * INP) {
            if (t + 1 < T_SEQ) xs[(t + 1) & 1][tid] = xreg;
            if (t + 2 < T_SEQ) xreg = x[(size_t)(t + 2) * BATCH * INP + b0 * INP + tid];
        }
        __syncthreads();
    }

    // final out row (t = T-1)
    if (tid < 64) {
        float p = red[(T_SEQ - 1) & 1][tid];
#pragma unroll
        for (int s = 8; s; s >>= 1) p += __shfl_xor_sync(0xffffffffu, p, s);
        if ((tid & 15) == 0)
            out[(size_t)((T_SEQ - 1) * BATCH + b0 + (tid >> 4)) * HEADS + h] = p + blin_v;
    }
}

extern "C" void kernel_launch(void* const* d_in, const int* in_sizes, int n_in,
                              void* d_out, int out_size) {
    const float* x    = (const float*)d_in[0];
    const float* Wih  = (const float*)d_in[1];
    const float* Whh  = (const float*)d_in[2];
    const float* bih  = (const float*)d_in[3];
    const float* bhh  = (const float*)d_in[4];
    const float* Wlin = (const float*)d_in[5];
    const float* blin = (const float*)d_in[6];

    float* out  = (float*)d_out;
    float* lout = out + OUT_ELEMS;

    cudaMemsetAsync(lout, 0, (size_t)LOUT_ELEMS * sizeof(float), 0);

    lstm_kernel<<<HEADS * (BATCH / BC), NTHREADS>>>(
        x, Wih, Whh, bih, bhh, Wlin, blin, out, lout);
}

// round 7
// speedup vs baseline: 1.3082x; 1.3082x over previous
#include <cuda_runtime.h>

#define T_SEQ   2048
#define BATCH   64
#define INP     16
#define HEADS   8
#define HID     64
#define GATES   256
#define BC      2
#define NTHREADS 256
#define OUT_ELEMS  (T_SEQ * BATCH * HEADS)
#define LOUT_ELEMS (T_SEQ * BATCH * HID)

// Packed fp32x2 FMA (sm_100+): 2 MACs/instr, 2x FFMA throughput.
__device__ __forceinline__ float2 ffma2(float2 a, float2 b, float2 c) {
    float2 d;
    asm("fma.rn.f32x2 %0, %1, %2, %3;"
        : "=l"(reinterpret_cast<unsigned long long&>(d))
        : "l"(reinterpret_cast<const unsigned long long&>(a)),
          "l"(reinterpret_cast<const unsigned long long&>(b)),
          "l"(reinterpret_cast<const unsigned long long&>(c)));
    return d;
}

__device__ __forceinline__ float fsig(float x) {
    return __fdividef(1.0f, 1.0f + __expf(-x));
}
__device__ __forceinline__ float ftanh_(float x) {
    return fmaf(2.0f, fsig(2.0f * x), -1.0f);
}

// CTA = (head, 2 batches), 256 threads, thread j = gate row j (both batches).
// grid = 8*32 = 256 CTAs -> 2 CTAs per SM on 108 SMs (one wave, occ=2):
// two independent recurrence chains per SM hide each other's stalls.
__global__ void __launch_bounds__(NTHREADS, 2)
lstm_kernel(const float* __restrict__ x,    const float* __restrict__ Wih,
            const float* __restrict__ Whh,  const float* __restrict__ bih,
            const float* __restrict__ bhh,  const float* __restrict__ Wlin,
            const float* __restrict__ blin, float* __restrict__ out,
            float* __restrict__ lout)
{
    const int h  = blockIdx.x >> 5;            // head 0..7
    const int b0 = (blockIdx.x & 31) * BC;     // first batch of this CTA
    const int j  = threadIdx.x;                // gate row 0..255
    const int d  = j & (HID - 1);              // phase-2 hidden index
    const int bb = j >> 6;                     // phase-2 batch (j<128)

    __shared__ __align__(16) float hs[2][BC * HID];  // [buf][b*64+d]
    __shared__ __align__(16) float zb[BC][GATES];    // [b][row]  (conflict-free p2)
    __shared__ __align__(16) float xs[2][BC * INP];  // x double buffer
    __shared__ float red[2][4];                      // [buf][warp partials]

    // ---- weights -> registers (row j) ----
    float2 w2[HID / 2];
    {
        const float4* wr = reinterpret_cast<const float4*>(Whh + (size_t)(h * GATES + j) * HID);
#pragma unroll
        for (int q = 0; q < HID / 4; ++q) {
            float4 v = wr[q];
            w2[2 * q]     = make_float2(v.x, v.y);
            w2[2 * q + 1] = make_float2(v.z, v.w);
        }
    }
    float2 wi2[INP / 2];
    {
        const float4* wr = reinterpret_cast<const float4*>(Wih + (size_t)(h * GATES + j) * INP);
#pragma unroll
        for (int q = 0; q < INP / 4; ++q) {
            float4 v = wr[q];
            wi2[2 * q]     = make_float2(v.x, v.y);
            wi2[2 * q + 1] = make_float2(v.z, v.w);
        }
    }
    const float bias   = bih[h * GATES + j] + bhh[h * GATES + j];
    const float wlin_d = Wlin[h * HID + d];
    const float blin_v = blin[h];

    // ---- init ----
    if (j < 2 * BC * HID) ((float*)hs)[j] = 0.0f;    // 256 entries == NTHREADS
    float c = 0.0f;
    float xreg = 0.0f;
    if (j < BC * INP) {
        xs[0][j] = x[(size_t)0 * BATCH * INP + b0 * INP + j];
        xreg     = x[(size_t)1 * BATCH * INP + b0 * INP + j];
    }
    __syncthreads();

    for (int t = 0; t < T_SEQ; ++t) {
        // deferred out[t-1]: red[(t-1)&1] finalized last step, visible now
        if (t > 0 && j < BC) {
            out[(size_t)((t - 1) * BATCH + b0 + j) * HEADS + h] =
                red[(t - 1) & 1][2 * j] + red[(t - 1) & 1][2 * j + 1] + blin_v;
        }

        // ---- phase 1: z_j[b] = bias + Whh_row_j.h[b] + Wih_row_j.x_t[b] ----
        const float* hb = hs[t & 1];
        const float* xb = xs[t & 1];
        float zr[BC];
#pragma unroll
        for (int b = 0; b < BC; ++b) {
            float2 a0 = make_float2(bias, 0.0f);
            float2 a1 = make_float2(0.0f, 0.0f);
            const float4* hv = reinterpret_cast<const float4*>(hb + b * HID);
#pragma unroll
            for (int q = 0; q < HID / 4; ++q) {
                float4 v = hv[q];
                a0 = ffma2(w2[2 * q],     make_float2(v.x, v.y), a0);
                a1 = ffma2(w2[2 * q + 1], make_float2(v.z, v.w), a1);
            }
            const float4* xv = reinterpret_cast<const float4*>(xb + b * INP);
#pragma unroll
            for (int q = 0; q < INP / 4; ++q) {
                float4 v = xv[q];
                a0 = ffma2(wi2[2 * q],     make_float2(v.x, v.y), a0);
                a1 = ffma2(wi2[2 * q + 1], make_float2(v.z, v.w), a1);
            }
            zr[b] = (a0.x + a0.y) + (a1.x + a1.y);
        }
#pragma unroll
        for (int b = 0; b < BC; ++b) zb[b][j] = zr[b];
        __syncthreads();

        // ---- phase 2: gates + state (threads j<128: (bb,d)) ----
        if (j < BC * HID) {
            float zi = zb[bb][0 * HID + d];
            float zf = zb[bb][1 * HID + d];
            float zg = zb[bb][2 * HID + d];
            float zo = zb[bb][3 * HID + d];
            float ig = fsig(zi) * ftanh_(zg);
            c = fmaf(fsig(zf), c, ig);
            float hval = fsig(zo) * ftanh_(c);
            hs[(t + 1) & 1][bb * HID + d] = hval;

            // lstm_output head-sum: fire-and-forget RED, distinct addresses
            atomicAdd(lout + (size_t)(t * BATCH + b0 + bb) * HID + d, hval);

            // per-head linear partial: reduce over d within each warp
            float p = hval * wlin_d;
#pragma unroll
            for (int s = 16; s; s >>= 1) p += __shfl_down_sync(0xffffffffu, p, s);
            if ((j & 31) == 0) red[t & 1][j >> 5] = p;   // warps 0..3
        }

        // x pipeline: publish x_{t+1} (loaded a step ago), prefetch x_{t+2}
        if (j < BC * INP) {
            if (t + 1 < T_SEQ) xs[(t + 1) & 1][j] = xreg;
            if (t + 2 < T_SEQ) xreg = x[(size_t)(t + 2) * BATCH * INP + b0 * INP + j];
        }
        __syncthreads();
    }

    // final out row (t = T-1)
    if (j < BC) {
        out[(size_t)((T_SEQ - 1) * BATCH + b0 + j) * HEADS + h] =
            red[(T_SEQ - 1) & 1][2 * j] + red[(T_SEQ - 1) & 1][2 * j + 1] + blin_v;
    }
}

extern "C" void kernel_launch(void* const* d_in, const int* in_sizes, int n_in,
                              void* d_out, int out_size) {
    const float* x    = (const float*)d_in[0];
    const float* Wih  = (const float*)d_in[1];
    const float* Whh  = (const float*)d_in[2];
    const float* bih  = (const float*)d_in[3];
    const float* bhh  = (const float*)d_in[4];
    const float* Wlin = (const float*)d_in[5];
    const float* blin = (const float*)d_in[6];

    float* out  = (float*)d_out;                 // (T,B,H)
    float* lout = out + OUT_ELEMS;               // (T,B,HID), accumulated

    cudaMemsetAsync(lout, 0, (size_t)LOUT_ELEMS * sizeof(float), 0);

    lstm_kernel<<<HEADS * (BATCH / BC), NTHREADS>>>(
        x, Wih, Whh, bih, bhh, Wlin, blin, out, lout);
}

// round 8
// speedup vs baseline: 1.3511x; 1.0328x over previous
#include <cuda_runtime.h>

#define T_SEQ   2048
#define BATCH   64
#define INP     16
#define HEADS   8
#define HID     64
#define GATES   256
#define BC      2
#define NTHREADS 256
#define OUT_ELEMS  (T_SEQ * BATCH * HEADS)
#define LOUT_ELEMS (T_SEQ * BATCH * HID)

// Packed fp32x2 FMA (sm_100+): 2 MACs/instr, 2x FFMA throughput.
__device__ __forceinline__ float2 ffma2(float2 a, float2 b, float2 c) {
    float2 d;
    asm("fma.rn.f32x2 %0, %1, %2, %3;"
        : "=l"(reinterpret_cast<unsigned long long&>(d))
        : "l"(reinterpret_cast<const unsigned long long&>(a)),
          "l"(reinterpret_cast<const unsigned long long&>(b)),
          "l"(reinterpret_cast<const unsigned long long&>(c)));
    return d;
}

__device__ __forceinline__ float fsig(float x) {
    return __fdividef(1.0f, 1.0f + __expf(-x));
}
__device__ __forceinline__ float ftanh_(float x) {
    return fmaf(2.0f, fsig(2.0f * x), -1.0f);
}

// CTA = (head, 2 batches), 256 threads, thread j = gate row j (both batches).
// grid 256 -> 2 CTAs/SM on most SMs; two independent chains hide stalls.
//
// Phase 1: thread j computes z for its gate row (both batches) AND applies
//          its row's nonlinearity (tanh for g-rows, sigmoid otherwise) before
//          storing to zb -> the phase-2 chain has a single tanh left.
// Phase 2: j<128 (one thread per (bb,d)): c/h update + store h.
//          j>=128: drain step t-1's outputs from the still-live hs[t&1]
//          buffer via fire-and-forget REDs (no shfl reduce at all).
__global__ void __launch_bounds__(NTHREADS, 2)
lstm_kernel(const float* __restrict__ x,    const float* __restrict__ Wih,
            const float* __restrict__ Whh,  const float* __restrict__ bih,
            const float* __restrict__ bhh,  const float* __restrict__ Wlin,
            const float* __restrict__ blin, float* __restrict__ out,
            float* __restrict__ lout)
{
    const int h    = blockIdx.x >> 5;          // head 0..7
    const int b0   = (blockIdx.x & 31) * BC;   // first batch of this CTA
    const int j    = threadIdx.x;              // gate row 0..255
    const int gate = j >> 6;                   // 0:i 1:f 2:g 3:o
    const int d    = j & (HID - 1);
    const int bb   = gate & 1;                 // phase-2 batch (both halves)

    __shared__ __align__(16) float hs[2][BC * HID];  // [buf][b*64+d]
    __shared__ __align__(16) float zb[BC][GATES];    // activated gates [b][row]
    __shared__ __align__(16) float xs[2][BC * INP];  // x double buffer

    // ---- weights -> registers (row j) ----
    float2 w2[HID / 2];
    {
        const float4* wr = reinterpret_cast<const float4*>(Whh + (size_t)(h * GATES + j) * HID);
#pragma unroll
        for (int q = 0; q < HID / 4; ++q) {
            float4 v = wr[q];
            w2[2 * q]     = make_float2(v.x, v.y);
            w2[2 * q + 1] = make_float2(v.z, v.w);
        }
    }
    float2 wi2[INP / 2];
    {
        const float4* wr = reinterpret_cast<const float4*>(Wih + (size_t)(h * GATES + j) * INP);
#pragma unroll
        for (int q = 0; q < INP / 4; ++q) {
            float4 v = wr[q];
            wi2[2 * q]     = make_float2(v.x, v.y);
            wi2[2 * q + 1] = make_float2(v.z, v.w);
        }
    }
    const float bias   = bih[h * GATES + j] + bhh[h * GATES + j];
    const float wlin_d = Wlin[h * HID + d];
    const float blin_j = (d == 0) ? blin[h] : 0.0f;

    // ---- init ----
    if (j < BC * HID) hs[0][j] = 0.0f;
    float c = 0.0f;
    float xreg = 0.0f;
    if (j < BC * INP) {
        xs[0][j] = x[(size_t)0 * BATCH * INP + b0 * INP + j];
        xreg     = x[(size_t)1 * BATCH * INP + b0 * INP + j];
    }
    __syncthreads();

#pragma unroll 2
    for (int t = 0; t < T_SEQ; ++t) {
        // ---- phase 1: z_j[b] = bias + Whh_j.h[b] + Wih_j.x_t[b], then act ----
        const float* hb = hs[t & 1];
        const float* xb = xs[t & 1];
        float zr[BC];
#pragma unroll
        for (int b = 0; b < BC; ++b) {
            float2 a0 = make_float2(bias, 0.0f);
            float2 a1 = make_float2(0.0f, 0.0f);
            const float4* hv = reinterpret_cast<const float4*>(hb + b * HID);
#pragma unroll
            for (int q = 0; q < HID / 4; ++q) {
                float4 v = hv[q];
                a0 = ffma2(w2[2 * q],     make_float2(v.x, v.y), a0);
                a1 = ffma2(w2[2 * q + 1], make_float2(v.z, v.w), a1);
            }
            const float4* xv = reinterpret_cast<const float4*>(xb + b * INP);
#pragma unroll
            for (int q = 0; q < INP / 4; ++q) {
                float4 v = xv[q];
                a0 = ffma2(wi2[2 * q],     make_float2(v.x, v.y), a0);
                a1 = ffma2(wi2[2 * q + 1], make_float2(v.z, v.w), a1);
            }
            zr[b] = (a0.x + a0.y) + (a1.x + a1.y);
        }
        // row-owned nonlinearity (warp-uniform branch: warps 4-5 are g-rows)
        if (gate == 2) { zr[0] = ftanh_(zr[0]); zr[1] = ftanh_(zr[1]); }
        else           { zr[0] = fsig(zr[0]);   zr[1] = fsig(zr[1]);   }
        zb[0][j] = zr[0];
        zb[1][j] = zr[1];
        __syncthreads();

        // ---- phase 2 ----
        if (j < BC * HID) {
            // gate threads: c/h update only (single tanh chain left)
            float si = zb[bb][0 * HID + d];
            float sf = zb[bb][1 * HID + d];
            float tg = zb[bb][2 * HID + d];
            float so = zb[bb][3 * HID + d];
            c = fmaf(sf, c, si * tg);
            hs[(t + 1) & 1][j] = so * ftanh_(c);   // j == bb*64+d here
        } else if (t > 0) {
            // drain step t-1 outputs from hs[t&1] (h_{t-1}), fire-and-forget
            float hprev = hb[j - 128];             // (bb,d) = ((j>>6)&1, j&63)
            atomicAdd(lout + (size_t)((t - 1) * BATCH + b0 + bb) * HID + d, hprev);
            atomicAdd(out  + (size_t)((t - 1) * BATCH + b0 + bb) * HEADS + h,
                      fmaf(hprev, wlin_d, blin_j));
        }

        // x pipeline: publish x_{t+1} (loaded a step ago), prefetch x_{t+2}
        if (j < BC * INP) {
            if (t + 1 < T_SEQ) xs[(t + 1) & 1][j] = xreg;
            if (t + 2 < T_SEQ) xreg = x[(size_t)(t + 2) * BATCH * INP + b0 * INP + j];
        }
        __syncthreads();
    }

    // drain final step (t = T-1): h_{T-1} lives in hs[T_SEQ & 1] = hs[0]
    if (j >= BC * HID) {
        float hlast = hs[T_SEQ & 1][j - 128];
        atomicAdd(lout + (size_t)((T_SEQ - 1) * BATCH + b0 + bb) * HID + d, hlast);
        atomicAdd(out  + (size_t)((T_SEQ - 1) * BATCH + b0 + bb) * HEADS + h,
                  fmaf(hlast, wlin_d, blin_j));
    }
}

extern "C" void kernel_launch(void* const* d_in, const int* in_sizes, int n_in,
                              void* d_out, int out_size) {
    const float* x    = (const float*)d_in[0];
    const float* Wih  = (const float*)d_in[1];
    const float* Whh  = (const float*)d_in[2];
    const float* bih  = (const float*)d_in[3];
    const float* bhh  = (const float*)d_in[4];
    const float* Wlin = (const float*)d_in[5];
    const float* blin = (const float*)d_in[6];

    float* out  = (float*)d_out;                 // (T,B,H), atomic-accumulated
    float* lout = out + OUT_ELEMS;               // (T,B,HID), atomic-accumulated

    // both regions are accumulated with REDs -> zero the whole output
    cudaMemsetAsync(d_out, 0, (size_t)(OUT_ELEMS + LOUT_ELEMS) * sizeof(float), 0);

    lstm_kernel<<<HEADS * (BATCH / BC), NTHREADS>>>(
        x, Wih, Whh, bih, bhh, Wlin, blin, out, lout);
}